// round 2
// baseline (speedup 1.0000x reference)
#include <cuda_runtime.h>
#include <cstdint>

// GramsEmbedding: out[b,s,:] = sum over UNIQUE v in {idx[0,b,s], idx[1,b,s]} of weight[v,:]
// K=2, B=2, S=1024, V=32000, D=128.
//
// One thread per OUTPUT ELEMENT (2048 rows x 128 cols = 262144 threads) to
// maximize occupancy (~86%) and hide the idx->gather dependent load chain.
// Each warp covers 32 consecutive columns of one row: idx load broadcasts
// (1 sector), weight gather + output store are fully coalesced 128B accesses.

#define ROWS      2048      // B * S
#define D         128
#define THREADS   256

__global__ __launch_bounds__(THREADS, 8)
void grams_embedding_kernel(const int* __restrict__ idx,
                            const float* __restrict__ w,     // [32000][128]
                            float* __restrict__ out)         // [2048][128]
{
    int t    = blockIdx.x * THREADS + threadIdx.x;   // 0 .. 262143
    int row  = t >> 7;                                // 0 .. 2047
    int col  = t & 127;                               // 0 .. 127

    int i0 = __ldg(&idx[row]);           // gram 0 (broadcast within warp)
    int i1 = __ldg(&idx[row + ROWS]);    // gram 1

    // Issue both gathers unconditionally for max MLP; zero out the duplicate.
    float a = __ldg(&w[(long)i0 * D + col]);
    float b = __ldg(&w[(long)i1 * D + col]);
    out[(long)row * D + col] = a + (i1 != i0 ? b : 0.0f);
}

extern "C" void kernel_launch(void* const* d_in, const int* in_sizes, int n_in,
                              void* d_out, int out_size)
{
    const int*   idx = (const int*)d_in[0];
    const float* w   = (const float*)d_in[1];
    float*       out = (float*)d_out;

    const int total_threads = ROWS * D;              // 262144
    grams_embedding_kernel<<<total_threads / THREADS, THREADS>>>(idx, w, out);
}